// round 9
// baseline (speedup 1.0000x reference)
#include <cuda_runtime.h>
#include <cuda_bf16.h>

#define BS   8
#define SEQ  2048
#define DIN  2048
#define DOUT 2048
#define RK   8
#define SCALING 2.0f   // 16.0 / R (folded into B registers at setup)

typedef unsigned long long u64;

// ---- f32x2 packed-math helpers (sm_100+) -----------------------------------
__device__ __forceinline__ u64 ffma2(u64 a, u64 b, u64 c) {
    u64 d;
    asm("fma.rn.f32x2 %0, %1, %2, %3;" : "=l"(d) : "l"(a), "l"(b), "l"(c));
    return d;
}
__device__ __forceinline__ u64 addx2(u64 a, u64 b) {
    u64 d;
    asm("add.rn.f32x2 %0, %1, %2;" : "=l"(d) : "l"(a), "l"(b));
    return d;
}
__device__ __forceinline__ u64 rep2(float x) {
    u64 r; asm("mov.b64 %0, {%1, %1};" : "=l"(r) : "f"(x)); return r;
}
__device__ __forceinline__ u64 pk2(float lo, float hi) {
    u64 r; asm("mov.b64 %0, {%1, %2};" : "=l"(r) : "f"(lo), "f"(hi)); return r;
}
__device__ __forceinline__ void upk2(u64 v, float& lo, float& hi) {
    asm("mov.b64 {%0, %1}, %2;" : "=f"(lo), "=f"(hi) : "l"(v));
}

// ---------------------------------------------------------------------------
// Single fused kernel (round-4 loop discipline: ONE barrier per iter, no
// serialized single-warp sections).
// Prologue: iter-0 x prefetch -> gate MLP -> A,B register slices from Wa/Wb.
// Loop (4 rows/iter):
//   p1 FFMA2 (acc packed over (r, r+4)) -> prefetch -> packed u64 butterfly
//   -> STS.64 part[buf] -> BAR -> every warp sums part (16 LDS.64 + ADDx2)
//   -> phase 2: packed pair used directly as multiplier, half0 = ranks 0-3,
//      half1 = ranks 4-7, one cross-half fold per output -> STG.128.
// ---------------------------------------------------------------------------
__global__ __launch_bounds__(512, 1) void k_main(
    const float* __restrict__ x, float* __restrict__ out,
    const float* __restrict__ ctr, const float* __restrict__ gamma,
    const float* __restrict__ beta, const float* __restrict__ W1,
    const float* __restrict__ b1, const float* __restrict__ W2,
    const float* __restrict__ b2, const float* __restrict__ Wa,
    const float* __restrict__ Wb)
{
    const int b = blockIdx.y;
    const int tid = threadIdx.x;
    const int warp = tid >> 5, lane = tid & 31;
    const int m16 = lane & 15;
    const int d0 = tid * 4;

    __shared__ float zs[32];
    __shared__ float hs[64];
    __shared__ float graw[4];
    __shared__ u64 part[2][16][16];   // [buf][warp][value m], packed (m, m+4 scalars)

    const float* xb = x + (size_t)b * SEQ * DIN;
    float* ob = out + (size_t)b * SEQ * DOUT;
    const int step = gridDim.x;

    // ---- iter-0 x prefetch (independent of everything below) ----
    float4 xv[4];
    int q = blockIdx.x;
    {
        const int s = q * 4;
        #pragma unroll
        for (int rr = 0; rr < 4; rr++)
            xv[rr] = __ldcs((const float4*)(xb + (size_t)(s + rr) * DIN + d0));
    }

    // ---- gate MLP (per-CTA recompute; short smem chains) ----
    if (tid < 32) {
        float v = ctr[b * 32 + tid];
        float s = v;
        #pragma unroll
        for (int o = 16; o; o >>= 1) s += __shfl_xor_sync(0xffffffffu, s, o);
        float mu = s * (1.0f / 32.0f);
        float dv = v - mu;
        float s2 = dv * dv;
        #pragma unroll
        for (int o = 16; o; o >>= 1) s2 += __shfl_xor_sync(0xffffffffu, s2, o);
        zs[tid] = dv * rsqrtf(s2 * (1.0f / 32.0f) + 1e-5f) * gamma[tid] + beta[tid];
    }
    __syncthreads();
    if (tid < 64) {
        float h = 0.0f;
        if (tid < 60) {
            h = b1[tid];
            #pragma unroll
            for (int c = 0; c < 32; c++) h = fmaf(zs[c], W1[tid * 32 + c], h);
            h = fmaxf(h, 0.0f);
        }
        hs[tid] = h;
    }
    __syncthreads();
    if (tid < 4) {
        float s = b2[tid];
        #pragma unroll
        for (int j = 0; j < 60; j++) s = fmaf(hs[j], W2[tid * 60 + j], s);
        graw[tid] = s;
    }
    __syncthreads();
    if (tid < 4) {
        float m = fmaxf(fmaxf(graw[0], graw[1]), fmaxf(graw[2], graw[3]));
        float den = expf(graw[0] - m) + expf(graw[1] - m) +
                    expf(graw[2] - m) + expf(graw[3] - m);
        hs[tid] = expf(graw[tid] - m) / den;
    }
    __syncthreads();
    const float g0 = hs[0], g1 = hs[1], g2 = hs[2], g3 = hs[3];

    // ---- A slice in regs: a2[j][rp] = { A[rp][d0+j], A[rp+4][d0+j] } ----
    u64 a2[4][4];
    #pragma unroll
    for (int j = 0; j < 4; j++) {
        float at[8];
        #pragma unroll
        for (int r = 0; r < 8; r++) {
            float4 w = *(const float4*)(Wa + ((size_t)(r * DIN + d0 + j) << 2));
            at[r] = g0 * w.x + g1 * w.y + g2 * w.z + g3 * w.w;
        }
        #pragma unroll
        for (int rp = 0; rp < 4; rp++) a2[j][rp] = pk2(at[rp], at[rp + 4]);
    }
    // ---- B slice in regs (pre-scaled), half-split layout:
    //      b2p[rp][k] = { S*B[rp][d0+k], S*B[rp+4][d0+k] } ----
    u64 b2p[4][4];
    #pragma unroll
    for (int rp = 0; rp < 4; rp++) {
        #pragma unroll
        for (int k = 0; k < 4; k++) {
            float4 wl = *(const float4*)(Wb + ((size_t)(rp * DOUT + d0 + k) << 2));
            float4 wh = *(const float4*)(Wb + ((size_t)((rp + 4) * DOUT + d0 + k) << 2));
            float lo = SCALING * (g0 * wl.x + g1 * wl.y + g2 * wl.z + g3 * wl.w);
            float hi = SCALING * (g0 * wh.x + g1 * wh.y + g2 * wh.z + g3 * wh.w);
            b2p[rp][k] = pk2(lo, hi);
        }
    }

    // ---- main loop ----
    int buf = 0;
    for (; q < SEQ / 4; q += step, buf ^= 1) {
        const int s = q * 4;

        // phase 1: acc2[m], m = rr*4+rp, halves = scalars (rr*8+rp, rr*8+rp+4)
        u64 acc2[16];
        #pragma unroll
        for (int v = 0; v < 16; v++) acc2[v] = 0ull;

        #pragma unroll
        for (int rr = 0; rr < 4; rr++) {
            const float* xr = (const float*)&xv[rr];
            #pragma unroll
            for (int j = 0; j < 4; j++) {
                u64 xj2 = rep2(xr[j]);
                #pragma unroll
                for (int rp = 0; rp < 4; rp++)
                    acc2[rr * 4 + rp] = ffma2(xj2, a2[j][rp], acc2[rr * 4 + rp]);
            }
        }

        // prefetch next iteration's rows (xv dead now)
        const int qn = q + step;
        if (qn < SEQ / 4) {
            const int sn = qn * 4;
            #pragma unroll
            for (int rr = 0; rr < 4; rr++)
                xv[rr] = __ldcs((const float4*)(xb + (size_t)(sn + rr) * DIN + d0));
        }

        // packed butterfly: 16 u64 values over 16-lane halves, then cross-half.
        // After: lanes l and l^16 hold warp-total of value (l & 15).
        #pragma unroll
        for (int off = 8; off >= 1; off >>= 1) {
            const bool up = (lane & off) != 0;
            #pragma unroll
            for (int i = 0; i < off; i++) {
                u64 send = up ? acc2[i] : acc2[off + i];
                u64 recv = __shfl_xor_sync(0xffffffffu, send, off);
                u64 keep = up ? acc2[off + i] : acc2[i];
                acc2[i] = addx2(keep, recv);
            }
        }
        acc2[0] = addx2(acc2[0], __shfl_xor_sync(0xffffffffu, acc2[0], 16));

        if (lane < 16) part[buf][warp][lane] = acc2[0];
        __syncthreads();

        // EVERY warp: cross-warp sum (broadcast LDS.64, conflict-free).
        // Lane l ends with packed pair {xa[m_sc], xa[m_sc+4]}, m = l&15,
        // m_sc = (m>>2)*8 + (m&3).
        u64 xa2 = part[buf][0][m16];
        #pragma unroll
        for (int w = 1; w < 16; w++) xa2 = addx2(xa2, part[buf][w][m16]);

        // phase 2: packed pair is the multiplier; half0 = ranks 0-3,
        // half1 = ranks 4-7; fold halves at the end.
        #pragma unroll
        for (int rr = 0; rr < 4; rr++) {
            u64 xm[4];
            #pragma unroll
            for (int rp = 0; rp < 4; rp++)
                xm[rp] = __shfl_sync(0xffffffffu, xa2, rr * 4 + rp);

            u64 o2[4];
            #pragma unroll
            for (int k = 0; k < 4; k++) o2[k] = 0ull;
            #pragma unroll
            for (int rp = 0; rp < 4; rp++)
                #pragma unroll
                for (int k = 0; k < 4; k++)
                    o2[k] = ffma2(xm[rp], b2p[rp][k], o2[k]);

            float o[4];
            #pragma unroll
            for (int k = 0; k < 4; k++) {
                float lo, hi;
                upk2(o2[k], lo, hi);
                o[k] = lo + hi;
            }
            __stcs((float4*)(ob + (size_t)(s + rr) * DOUT + d0),
                   make_float4(o[0], o[1], o[2], o[3]));
        }
    }
}

// ---------------------------------------------------------------------------
extern "C" void kernel_launch(void* const* d_in, const int* in_sizes, int n_in,
                              void* d_out, int out_size)
{
    const float* x     = (const float*)d_in[0];
    const float* ctr   = (const float*)d_in[1];
    const float* gamma = (const float*)d_in[2];
    const float* beta  = (const float*)d_in[3];
    const float* W1    = (const float*)d_in[4];
    const float* b1    = (const float*)d_in[5];
    const float* W2    = (const float*)d_in[6];
    const float* b2    = (const float*)d_in[7];
    const float* Wa    = (const float*)d_in[8];
    const float* Wb    = (const float*)d_in[9];
    float* out = (float*)d_out;

    k_main<<<dim3(18, 8), 512>>>(x, out, ctr, gamma, beta, W1, b1, W2, b2, Wa, Wb);
}

// round 14
// speedup vs baseline: 1.1836x; 1.1836x over previous
#include <cuda_runtime.h>
#include <cuda_bf16.h>

#define BS   8
#define SEQ  2048
#define DIN  2048
#define DOUT 2048
#define SCALING 2.0f   // 16.0 / R (folded into B at staging)

typedef unsigned long long u64;

// ---- f32x2 packed-math helpers (sm_100+) -----------------------------------
__device__ __forceinline__ u64 ffma2(u64 a, u64 b, u64 c) {
    u64 d;
    asm("fma.rn.f32x2 %0, %1, %2, %3;" : "=l"(d) : "l"(a), "l"(b), "l"(c));
    return d;
}
__device__ __forceinline__ u64 addx2(u64 a, u64 b) {
    u64 d;
    asm("add.rn.f32x2 %0, %1, %2;" : "=l"(d) : "l"(a), "l"(b));
    return d;
}
__device__ __forceinline__ u64 rep2(float x) {
    u64 r; asm("mov.b64 %0, {%1, %1};" : "=l"(r) : "f"(x)); return r;
}
__device__ __forceinline__ u64 pk2(float lo, float hi) {
    u64 r; asm("mov.b64 %0, {%1, %2};" : "=l"(r) : "f"(lo), "f"(hi)); return r;
}
__device__ __forceinline__ void upk2(u64 v, float& lo, float& hi) {
    asm("mov.b64 {%0, %1}, %2;" : "=f"(lo), "=f"(hi) : "l"(v));
}

// ---------------------------------------------------------------------------
// Single fused kernel, warp-autonomous main loop (NO barriers in the loop).
//
// smem (dynamic 128 KB):
//   At2[j][rp][d4] u64 = { A[rp][d4*4+j],  A[rp+4][d4*4+j] }        (64 KB)
//   Bs2[k][rp][o4] u64 = { S*B[rp][o4*4+k], S*B[rp+4][o4*4+k] }     (64 KB)
// Staged cooperatively with fully-coalesced LDG.128 from Wa/Wb.
//
// Each warp owns 4-row groups (2 groups total). Per c (32 d4 per lane-step):
//   p1: 4x LDG.128 x rows, 16 conflict-free LDS.64 (A), rank-packed FFMA2.
//   In-warp packed butterfly (16 u64 values) -> lane m holds
//   {xa[row][rp], xa[row][rp+4]} for m = row*4+rp; broadcast all 16 via shfl.
//   p2: 16 LDS.64 (B), FFMA2 with packed multipliers, fold halves, STG.128.
// ---------------------------------------------------------------------------
__global__ __launch_bounds__(512, 1) void k_main(
    const float* __restrict__ x, float* __restrict__ out,
    const float* __restrict__ ctr, const float* __restrict__ gamma,
    const float* __restrict__ beta, const float* __restrict__ W1,
    const float* __restrict__ b1, const float* __restrict__ W2,
    const float* __restrict__ b2, const float* __restrict__ Wa,
    const float* __restrict__ Wb)
{
    extern __shared__ u64 sdyn[];          // [0,8192) = At2, [8192,16384) = Bs2
    u64* At2 = sdyn;
    u64* Bs2 = sdyn + 8192;
    __shared__ float zs[32];
    __shared__ float hs[64];
    __shared__ float graw[4];

    const int b = blockIdx.y;
    const int tid = threadIdx.x;
    const int warp = tid >> 5, lane = tid & 31;

    // ---- gate MLP (one-time; barriers fine here) ----
    if (tid < 32) {
        float v = ctr[b * 32 + tid];
        float s = v;
        #pragma unroll
        for (int o = 16; o; o >>= 1) s += __shfl_xor_sync(0xffffffffu, s, o);
        float mu = s * (1.0f / 32.0f);
        float dv = v - mu;
        float s2 = dv * dv;
        #pragma unroll
        for (int o = 16; o; o >>= 1) s2 += __shfl_xor_sync(0xffffffffu, s2, o);
        zs[tid] = dv * rsqrtf(s2 * (1.0f / 32.0f) + 1e-5f) * gamma[tid] + beta[tid];
    }
    __syncthreads();
    if (tid < 64) {
        float h = 0.0f;
        if (tid < 60) {
            h = b1[tid];
            #pragma unroll
            for (int c = 0; c < 32; c++) h = fmaf(zs[c], W1[tid * 32 + c], h);
            h = fmaxf(h, 0.0f);
        }
        hs[tid] = h;
    }
    __syncthreads();
    if (tid < 4) {
        float s = b2[tid];
        #pragma unroll
        for (int j = 0; j < 60; j++) s = fmaf(hs[j], W2[tid * 60 + j], s);
        graw[tid] = s;
    }
    __syncthreads();
    if (tid < 4) {
        float m = fmaxf(fmaxf(graw[0], graw[1]), fmaxf(graw[2], graw[3]));
        float den = expf(graw[0] - m) + expf(graw[1] - m) +
                    expf(graw[2] - m) + expf(graw[3] - m);
        hs[tid] = expf(graw[tid] - m) / den;
    }
    __syncthreads();
    const float g0 = hs[0], g1 = hs[1], g2 = hs[2], g3 = hs[3];

    // ---- stage A into smem (coalesced: consecutive tid -> consecutive d) ----
    #pragma unroll 4
    for (int i = 0; i < 16; i++) {
        int e = tid + i * 512;
        int rp = e >> 11, d = e & 2047;
        float4 wl = *(const float4*)(Wa + ((size_t)(rp * DIN + d) << 2));
        float4 wh = *(const float4*)(Wa + ((size_t)((rp + 4) * DIN + d) << 2));
        float alo = g0 * wl.x + g1 * wl.y + g2 * wl.z + g3 * wl.w;
        float ahi = g0 * wh.x + g1 * wh.y + g2 * wh.z + g3 * wh.w;
        At2[(((d & 3) * 4 + rp) << 9) + (d >> 2)] = pk2(alo, ahi);
    }
    // ---- stage B into smem (pre-scaled) ----
    #pragma unroll 4
    for (int i = 0; i < 16; i++) {
        int e = tid + i * 512;
        int rp = e >> 11, o = e & 2047;
        float4 wl = *(const float4*)(Wb + ((size_t)(rp * DOUT + o) << 2));
        float4 wh = *(const float4*)(Wb + ((size_t)((rp + 4) * DOUT + o) << 2));
        float blo = SCALING * (g0 * wl.x + g1 * wl.y + g2 * wl.z + g3 * wl.w);
        float bhi = SCALING * (g0 * wh.x + g1 * wh.y + g2 * wh.z + g3 * wh.w);
        Bs2[(((o & 3) * 4 + rp) << 9) + (o >> 2)] = pk2(blo, bhi);
    }
    __syncthreads();   // last barrier in the kernel

    const float* xb = x + (size_t)b * SEQ * DIN;
    float* ob = out + (size_t)b * SEQ * DOUT;

    const int gw = blockIdx.x * 16 + warp;   // 0..255; groups gw and gw+256

    #pragma unroll 1
    for (int it = 0; it < 2; it++) {
        const int s = (gw + it * 256) * 4;

        u64 acc2[16];
        #pragma unroll
        for (int v = 0; v < 16; v++) acc2[v] = 0ull;

        // ---- phase 1 ----
        #pragma unroll 4
        for (int c = 0; c < 16; c++) {
            const int d4 = c * 32 + lane;
            float4 xr[4];
            #pragma unroll
            for (int row = 0; row < 4; row++)
                xr[row] = __ldcs((const float4*)(xb + (size_t)(s + row) * DIN + (size_t)d4 * 4));
            #pragma unroll
            for (int j = 0; j < 4; j++) {
                u64 aj[4];
                #pragma unroll
                for (int rp = 0; rp < 4; rp++)
                    aj[rp] = At2[((j * 4 + rp) << 9) + d4];
                #pragma unroll
                for (int row = 0; row < 4; row++) {
                    u64 xj2 = rep2(((const float*)&xr[row])[j]);
                    #pragma unroll
                    for (int rp = 0; rp < 4; rp++)
                        acc2[row * 4 + rp] = ffma2(xj2, aj[rp], acc2[row * 4 + rp]);
                }
            }
        }

        // ---- packed butterfly: 16 u64 values over 16-lane halves + fold ----
        // After: lanes l and l^16 hold warp-total of value (l & 15).
        #pragma unroll
        for (int off = 8; off >= 1; off >>= 1) {
            const bool up = (lane & off) != 0;
            #pragma unroll
            for (int i = 0; i < off; i++) {
                u64 send = up ? acc2[i] : acc2[off + i];
                u64 recv = __shfl_xor_sync(0xffffffffu, send, off);
                u64 keep = up ? acc2[off + i] : acc2[i];
                acc2[i] = addx2(keep, recv);
            }
        }
        acc2[0] = addx2(acc2[0], __shfl_xor_sync(0xffffffffu, acc2[0], 16));

        // broadcast all 16 packed sums: xm[m] = {xa[row][rp], xa[row][rp+4]},
        // m = row*4 + rp
        u64 xm[16];
        #pragma unroll
        for (int m = 0; m < 16; m++)
            xm[m] = __shfl_sync(0xffffffffu, acc2[0], m);

        // ---- phase 2 ----
        #pragma unroll 4
        for (int c = 0; c < 16; c++) {
            const int o4 = c * 32 + lane;
            u64 bk[16];
            #pragma unroll
            for (int k = 0; k < 4; k++)
                #pragma unroll
                for (int rp = 0; rp < 4; rp++)
                    bk[k * 4 + rp] = Bs2[((k * 4 + rp) << 9) + o4];
            #pragma unroll
            for (int row = 0; row < 4; row++) {
                u64 o2[4];
                #pragma unroll
                for (int k = 0; k < 4; k++) o2[k] = 0ull;
                #pragma unroll
                for (int rp = 0; rp < 4; rp++)
                    #pragma unroll
                    for (int k = 0; k < 4; k++)
                        o2[k] = ffma2(xm[row * 4 + rp], bk[k * 4 + rp], o2[k]);
                float o[4];
                #pragma unroll
                for (int k = 0; k < 4; k++) {
                    float lo, hi;
                    upk2(o2[k], lo, hi);
                    o[k] = lo + hi;
                }
                __stcs((float4*)(ob + (size_t)(s + row) * DOUT + (size_t)o4 * 4),
                       make_float4(o[0], o[1], o[2], o[3]));
            }
        }
    }
}

// ---------------------------------------------------------------------------
extern "C" void kernel_launch(void* const* d_in, const int* in_sizes, int n_in,
                              void* d_out, int out_size)
{
    const float* x     = (const float*)d_in[0];
    const float* ctr   = (const float*)d_in[1];
    const float* gamma = (const float*)d_in[2];
    const float* beta  = (const float*)d_in[3];
    const float* W1    = (const float*)d_in[4];
    const float* b1    = (const float*)d_in[5];
    const float* W2    = (const float*)d_in[6];
    const float* b2    = (const float*)d_in[7];
    const float* Wa    = (const float*)d_in[8];
    const float* Wb    = (const float*)d_in[9];
    float* out = (float*)d_out;

    const int smem_bytes = 128 * 1024;
    cudaFuncSetAttribute(k_main, cudaFuncAttributeMaxDynamicSharedMemorySize,
                         smem_bytes);
    k_main<<<dim3(16, 8), 512, smem_bytes>>>(x, out, ctr, gamma, beta,
                                             W1, b1, W2, b2, Wa, Wb);
}